// round 3
// baseline (speedup 1.0000x reference)
#include <cuda_runtime.h>
#include <cuda_bf16.h>

#define BATCH 128
#define NANCH 8732
#define NCLS  21
#define KTOP  200
#define CONF_T 0.01f
#define NMS_T  0.45f

// ---------------- scratch (device globals; no allocations allowed) ----------
__device__ float4 g_boxes[BATCH * NANCH];                       // ~17.9 MB
__device__ float  g_probs[(size_t)BATCH * 20 * NANCH];          // ~89.4 MB
__device__ float  g_sc[BATCH * 20 * KTOP];                      // kept scores
__device__ float4 g_sb[BATCH * 20 * KTOP];                      // kept boxes

// ---------------- kernel 1: decode + softmax ---------------------------------
__global__ void prep_kernel(const float* __restrict__ loc,
                            const float* __restrict__ conf,
                            const float* __restrict__ dbox) {
    __shared__ float sc[128 * NCLS];
    int b   = blockIdx.y;
    int n0  = blockIdx.x * 128;
    int tid = threadIdx.x;              // 128 threads
    int nrows = NANCH - n0; if (nrows > 128) nrows = 128;

    const float* cp = conf + ((size_t)b * NANCH + n0) * NCLS;
    for (int i = tid; i < nrows * NCLS; i += 128) sc[i] = cp[i];
    __syncthreads();

    if (tid < nrows) {
        int n = n0 + tid;
        const float* x = &sc[tid * NCLS];
        float m = x[0];
#pragma unroll
        for (int c = 1; c < NCLS; c++) m = fmaxf(m, x[c]);
        float e[NCLS];
        float s = 0.f;
#pragma unroll
        for (int c = 0; c < NCLS; c++) { e[c] = expf(x[c] - m); s += e[c]; }

        // decode box
        float4 l = reinterpret_cast<const float4*>(loc)[(size_t)b * NANCH + n];
        float4 d = reinterpret_cast<const float4*>(dbox)[n];
        float cx = d.x + l.x * 0.1f * d.z;
        float cy = d.y + l.y * 0.1f * d.w;
        float w  = d.z * expf(l.z * 0.2f);
        float h  = d.w * expf(l.w * 0.2f);
        float x1 = cx - w * 0.5f;
        float y1 = cy - h * 0.5f;
        float x2 = x1 + w;
        float y2 = y1 + h;
        x1 = fminf(fmaxf(x1, 0.f), 1.f);
        y1 = fminf(fmaxf(y1, 0.f), 1.f);
        x2 = fminf(fmaxf(x2, 0.f), 1.f);
        y2 = fminf(fmaxf(y2, 0.f), 1.f);
        g_boxes[(size_t)b * NANCH + n] = make_float4(x1, y1, x2, y2);

#pragma unroll
        for (int c = 1; c < NCLS; c++)
            g_probs[((size_t)b * 20 + (c - 1)) * NANCH + n] = e[c] / s;
    }
}

// ---------------- shared helpers ---------------------------------------------
__device__ __forceinline__ unsigned warp_suffix_incl(unsigned x) {
    unsigned lane = threadIdx.x & 31;
#pragma unroll
    for (int d = 1; d < 32; d <<= 1) {
        unsigned t = __shfl_down_sync(0xffffffffu, x, d);
        if (lane + d < 32) x += t;
    }
    return x;   // sum of x over lanes [lane..31]
}

// exclusive suffix over 256 threads: sum of x over threads with tid' > tid.
// Caller must __syncthreads() between successive uses (s_warp reuse).
__device__ __forceinline__ unsigned block_excl_suffix_256(unsigned x, unsigned* s_warp) {
    int lane = threadIdx.x & 31, wid = threadIdx.x >> 5;
    unsigned inc = warp_suffix_incl(x);
    if (lane == 0) s_warp[wid] = inc;
    __syncthreads();
    unsigned above = 0;
#pragma unroll
    for (int w = 0; w < 8; w++) if (w > wid) above += s_warp[w];
    return (inc - x) + above;
}

// bitonic sort of 512 u64 keys in shared, descending; blockDim = 256.
__device__ __forceinline__ void sort512_desc(unsigned long long* a) {
    int tid = threadIdx.x;
#pragma unroll
    for (int kk = 2; kk <= 512; kk <<= 1) {
        for (int j = kk >> 1; j > 0; j >>= 1) {
            __syncthreads();
            int i   = ((tid & ~(j - 1)) << 1) | (tid & (j - 1));
            int ixj = i | j;
            unsigned long long x = a[i], y = a[ixj];
            bool desc = ((i & kk) == 0);
            if (desc ? (x < y) : (x > y)) { a[i] = y; a[ixj] = x; }
        }
    }
    __syncthreads();
}

// ---------------- kernel 2: per-(batch,class) top-200 + greedy NMS -----------
// All valid scores s satisfy 0.01 < s <= 1 => bit31=0, bits[30:26]=01111.
// Only bits[25:0] vary. Round 0 histograms bits[25:16] (1024 bins).
#define NMSW 7                            // ceil(224/32) mask words per row
__global__ __launch_bounds__(256) void nms_kernel() {
    __shared__ union { unsigned hist[1024]; unsigned mask[KTOP * NMSW]; } su;
    __shared__ unsigned long long cand[512];
    __shared__ float4 sbox[KTOP];
    __shared__ float  sarea[KTOP];
    __shared__ unsigned s_warp[8];
    __shared__ unsigned s_alivew[8];
    __shared__ int selBin, selKk;
    __shared__ unsigned selCnt, s_total, s_cnt;

    int c    = blockIdx.x;               // 0..19 -> class c+1
    int b    = blockIdx.y;
    int tid  = threadIdx.x;              // 256 threads
    int lane = tid & 31, wid = tid >> 5;
    const float* __restrict__ row = g_probs + ((size_t)b * 20 + c) * NANCH;

    for (int i = tid; i < 1024; i += 256) su.hist[i] = 0;
    __syncthreads();

    // ---- pass 0: histogram bits[25:16], unrolled x8 for MLP ----
    for (int n = tid; n < NANCH; n += 2048) {
        float v[8];
#pragma unroll
        for (int u = 0; u < 8; u++) {
            int idx = n + u * 256;
            v[u] = (idx < NANCH) ? row[idx] : 0.f;
        }
#pragma unroll
        for (int u = 0; u < 8; u++)
            if (v[u] > CONF_T)
                atomicAdd(&su.hist[(__float_as_uint(v[u]) >> 16) & 1023u], 1u);
    }
    __syncthreads();

    {   // parallel suffix selection over 1024 bins (4 bins/thread)
        unsigned h0 = su.hist[4*tid], h1 = su.hist[4*tid+1];
        unsigned h2 = su.hist[4*tid+2], h3 = su.hist[4*tid+3];
        unsigned s3 = h3, s2 = h2 + s3, s1 = h1 + s2, s0 = h0 + s1;
        unsigned E = block_excl_suffix_256(s0, s_warp);
        if (tid == 0) s_total = s0 + E;
        unsigned f0 = s0+E, f1 = s1+E, f2 = s2+E, f3 = s3+E, f4 = E;
        if (f0 >= KTOP && f1 < KTOP) { selBin = 4*tid+0; selKk = KTOP-(int)f1; selCnt = f0; }
        if (f1 >= KTOP && f2 < KTOP) { selBin = 4*tid+1; selKk = KTOP-(int)f2; selCnt = f1; }
        if (f2 >= KTOP && f3 < KTOP) { selBin = 4*tid+2; selKk = KTOP-(int)f3; selCnt = f2; }
        if (f3 >= KTOP && f4 < KTOP) { selBin = 4*tid+3; selKk = KTOP-(int)f4; selCnt = f3; }
    }
    __syncthreads();

    unsigned pivot;
    if (s_total <= (unsigned)KTOP) {
        pivot = 0u;                                  // take every thresholded key
    } else if (selCnt <= 512u) {
        // common path: all keys with top-10 bits >= selBin (count <= 512);
        // exact top-200 emerges from the full sort below.
        pivot = (0x0Fu << 26) | ((unsigned)selBin << 16);
    } else {
        // rare path: refine 8+8 more bits to get the exact 200th key
        int d0 = selBin, kk1 = selKk;
        su.hist[tid] = 0;
        __syncthreads();
        for (int n = tid; n < NANCH; n += 256) {
            float s = row[n];
            if (s > CONF_T) {
                unsigned k = __float_as_uint(s);
                if (((k >> 16) & 1023u) == (unsigned)d0)
                    atomicAdd(&su.hist[(k >> 8) & 255u], 1u);
            }
        }
        __syncthreads();
        {
            unsigned h = su.hist[tid];
            unsigned E = block_excl_suffix_256(h, s_warp);
            if (h + E >= (unsigned)kk1 && E < (unsigned)kk1) { selBin = tid; selKk = kk1-(int)E; }
        }
        __syncthreads();
        int d1 = selBin, kk2 = selKk;
        unsigned pref = ((unsigned)d0 << 8) | (unsigned)d1;
        su.hist[tid] = 0;
        __syncthreads();
        for (int n = tid; n < NANCH; n += 256) {
            float s = row[n];
            if (s > CONF_T) {
                unsigned k = __float_as_uint(s);
                if (((k >> 8) & 0x3FFFFu) == pref)
                    atomicAdd(&su.hist[k & 255u], 1u);
            }
        }
        __syncthreads();
        {
            unsigned h = su.hist[tid];
            unsigned E = block_excl_suffix_256(h, s_warp);
            if (h + E >= (unsigned)kk2 && E < (unsigned)kk2) { selBin = tid; }
        }
        __syncthreads();
        pivot = (0x0Fu << 26) | ((unsigned)d0 << 16) | ((unsigned)d1 << 8) | (unsigned)selBin;
    }

    if (tid == 0) s_cnt = 0;
    __syncthreads();

    // ---- pass 1: collect candidates >= pivot, unrolled x8 ----
    // 64-bit key = (scorebits, ~index): stable descending == jax.lax.top_k
    for (int n = tid; n < NANCH; n += 2048) {
        float v[8];
#pragma unroll
        for (int u = 0; u < 8; u++) {
            int idx = n + u * 256;
            v[u] = (idx < NANCH) ? row[idx] : 0.f;
        }
#pragma unroll
        for (int u = 0; u < 8; u++) {
            if (v[u] > CONF_T) {
                unsigned k = __float_as_uint(v[u]);
                if (k >= pivot) {
                    unsigned p = atomicAdd(&s_cnt, 1u);
                    if (p < 512u)
                        cand[p] = ((unsigned long long)k << 32) | (unsigned)(~(n + u*256));
                }
            }
        }
    }
    __syncthreads();
    unsigned mcnt = s_cnt < 512u ? s_cnt : 512u;
    for (int i = tid; i < 512; i += 256)
        if ((unsigned)i >= mcnt) cand[i] = 0ull;
    sort512_desc(cand);                  // barriers inside, incl. trailing

    // ---- NMS setup: top-200 in regs + shared ----
    bool   myAlive = false;
    float4 myBox   = make_float4(0.f, 0.f, 0.f, 0.f);
    float  myArea  = 0.f;
    float  myScore = 0.f;
    if (tid < KTOP) {
        unsigned long long vv = cand[tid];
        if (vv) {
            unsigned n = ~(unsigned)(vv & 0xFFFFFFFFu);
            myBox   = g_boxes[(size_t)b * NANCH + n];
            myArea  = (myBox.z - myBox.x) * (myBox.w - myBox.y);
            myScore = __uint_as_float((unsigned)(vv >> 32));
            myAlive = true;
        }
        sbox[tid]  = myBox;
        sarea[tid] = myArea;
    }
    // initial alive bitmap (bits >= 200 are 0)
    {
        unsigned ball = __ballot_sync(0xffffffffu, tid < KTOP && myAlive);
        if (lane == 0) s_alivew[wid] = (wid < NMSW) ? ball : 0u;
    }
    __syncthreads();

    // ---- suppression matrix: mask[i][w] bit l = suppress j=w*32+l (j>i) ----
    for (int p = wid; p < KTOP * NMSW; p += 8) {
        int i = p / NMSW, w = p - i * NMSW;
        int j = w * 32 + lane;
        bool sup = false;
        if (j > i && j < KTOP) {
            float4 bi = sbox[i];
            float4 bj = sbox[j];
            float xx1 = fmaxf(bj.x, bi.x), yy1 = fmaxf(bj.y, bi.y);
            float xx2 = fminf(bj.z, bi.z), yy2 = fminf(bj.w, bi.w);
            float inter = fmaxf(xx2 - xx1, 0.f) * fmaxf(yy2 - yy1, 0.f);
            float iou = inter / (sarea[j] + sarea[i] - inter);
            sup = !(iou <= NMS_T);       // NaN -> suppress (torch semantics)
        }
        unsigned m = __ballot_sync(0xffffffffu, sup);
        if (lane == 0) su.mask[p] = m;
    }
    __syncthreads();

    // ---- greedy scan (warp 0, registers only, no block barriers) ----
    if (wid == 0) {
        unsigned aw = (lane < NMSW) ? s_alivew[lane] : 0u;
        for (int i = 0; i < KTOP; i++) {
            unsigned wbits = __shfl_sync(0xffffffffu, aw, i >> 5);
            if ((wbits >> (i & 31)) & 1u) {           // i survives -> apply row
                unsigned m = (lane < NMSW) ? su.mask[i * NMSW + lane] : 0u;
                aw &= ~m;
            }
        }
        if (lane < NMSW) s_alivew[lane] = aw;
    }
    __syncthreads();

    if (tid < KTOP) {
        bool kept = (s_alivew[tid >> 5] >> (tid & 31)) & 1u;
        int o = (b * 20 + c) * KTOP + tid;
        g_sc[o] = kept ? myScore : 0.f;
        g_sb[o] = kept ? myBox : make_float4(0.f, 0.f, 0.f, 0.f);
    }
}

// ---------------- kernel 3: global top-200 + per-class compaction ------------
__global__ __launch_bounds__(256) void final_kernel(float* __restrict__ out) {
    __shared__ unsigned hist[1024];
    __shared__ unsigned long long cand[512];
    __shared__ unsigned s_warp[8];
    __shared__ int selBin, selKk;
    __shared__ unsigned selCnt, s_total, s_cnt;

    int b   = blockIdx.x;
    int tid = threadIdx.x;              // 256 threads
    const float* __restrict__ sc = g_sc + b * 4000;

    for (int i = tid; i < 1024; i += 256) hist[i] = 0;
    __syncthreads();
    for (int n = tid; n < 4000; n += 256) {
        float s = sc[n];                // kept scores are 0 or in (0.01, 1]
        if (s > 0.f) atomicAdd(&hist[(__float_as_uint(s) >> 16) & 1023u], 1u);
    }
    __syncthreads();
    {
        unsigned h0 = hist[4*tid], h1 = hist[4*tid+1], h2 = hist[4*tid+2], h3 = hist[4*tid+3];
        unsigned s3 = h3, s2 = h2 + s3, s1 = h1 + s2, s0 = h0 + s1;
        unsigned E = block_excl_suffix_256(s0, s_warp);
        if (tid == 0) s_total = s0 + E;
        unsigned f0 = s0+E, f1 = s1+E, f2 = s2+E, f3 = s3+E, f4 = E;
        if (f0 >= KTOP && f1 < KTOP) { selBin = 4*tid+0; selKk = KTOP-(int)f1; selCnt = f0; }
        if (f1 >= KTOP && f2 < KTOP) { selBin = 4*tid+1; selKk = KTOP-(int)f2; selCnt = f1; }
        if (f2 >= KTOP && f3 < KTOP) { selBin = 4*tid+2; selKk = KTOP-(int)f3; selCnt = f2; }
        if (f3 >= KTOP && f4 < KTOP) { selBin = 4*tid+3; selKk = KTOP-(int)f4; selCnt = f3; }
    }
    __syncthreads();

    unsigned pivot;
    if (s_total <= (unsigned)KTOP) {
        pivot = 0u;
    } else if (selCnt <= 512u) {
        pivot = (0x0Fu << 26) | ((unsigned)selBin << 16);
    } else {
        int d0 = selBin, kk1 = selKk;
        hist[tid] = 0;
        __syncthreads();
        for (int n = tid; n < 4000; n += 256) {
            float s = sc[n];
            if (s > 0.f) {
                unsigned k = __float_as_uint(s);
                if (((k >> 16) & 1023u) == (unsigned)d0)
                    atomicAdd(&hist[(k >> 8) & 255u], 1u);
            }
        }
        __syncthreads();
        {
            unsigned h = hist[tid];
            unsigned E = block_excl_suffix_256(h, s_warp);
            if (h + E >= (unsigned)kk1 && E < (unsigned)kk1) { selBin = tid; selKk = kk1-(int)E; }
        }
        __syncthreads();
        int d1 = selBin, kk2 = selKk;
        unsigned pref = ((unsigned)d0 << 8) | (unsigned)d1;
        hist[tid] = 0;
        __syncthreads();
        for (int n = tid; n < 4000; n += 256) {
            float s = sc[n];
            if (s > 0.f) {
                unsigned k = __float_as_uint(s);
                if (((k >> 8) & 0x3FFFFu) == pref)
                    atomicAdd(&hist[k & 255u], 1u);
            }
        }
        __syncthreads();
        {
            unsigned h = hist[tid];
            unsigned E = block_excl_suffix_256(h, s_warp);
            if (h + E >= (unsigned)kk2 && E < (unsigned)kk2) { selBin = tid; }
        }
        __syncthreads();
        pivot = (0x0Fu << 26) | ((unsigned)d0 << 16) | ((unsigned)d1 << 8) | (unsigned)selBin;
    }

    if (tid == 0) s_cnt = 0;
    __syncthreads();
    for (int n = tid; n < 4000; n += 256) {
        float s = sc[n];
        if (s > 0.f) {
            unsigned k = __float_as_uint(s);
            if (k >= pivot) {
                unsigned p = atomicAdd(&s_cnt, 1u);
                if (p < 512u) cand[p] = ((unsigned long long)k << 32) | (unsigned)(~n);
            }
        }
    }
    __syncthreads();
    unsigned mcnt = s_cnt < 512u ? s_cnt : 512u;
    for (int i = tid; i < 512; i += 256)
        if ((unsigned)i >= mcnt) cand[i] = 0ull;
    sort512_desc(cand);

    // zero the whole batch output (poisoned by harness), then compact
    float* o = out + (size_t)b * NCLS * KTOP * 5;
    for (int i = tid; i < NCLS * KTOP * 5; i += 256) o[i] = 0.f;
    __syncthreads();

    if (tid < 20) {
        int cnt = 0;
        for (int k = 0; k < KTOP; k++) {            // global top-200 only
            unsigned long long vv = cand[k];
            if (!vv) break;                          // zeros sort last
            unsigned idx = ~(unsigned)(vv & 0xFFFFFFFFu);
            if ((int)(idx / KTOP) == tid) {          // class tid+1
                float s = __uint_as_float((unsigned)(vv >> 32));
                float4 bx = g_sb[b * 4000 + idx];
                float* dst = o + ((size_t)(tid + 1) * KTOP + cnt) * 5;
                dst[0] = s;
                dst[1] = bx.x; dst[2] = bx.y; dst[3] = bx.z; dst[4] = bx.w;
                cnt++;
            }
        }
    }
}

// ---------------- launch ------------------------------------------------------
extern "C" void kernel_launch(void* const* d_in, const int* in_sizes, int n_in,
                              void* d_out, int out_size) {
    const float* loc  = (const float*)d_in[0];   // [128, 8732, 4]
    const float* conf = (const float*)d_in[1];   // [128, 8732, 21]
    const float* dbox = (const float*)d_in[2];   // [8732, 4]
    float* out = (float*)d_out;                  // [128, 21, 200, 5]

    dim3 g1((NANCH + 127) / 128, BATCH);
    prep_kernel<<<g1, 128>>>(loc, conf, dbox);

    dim3 g2(20, BATCH);
    nms_kernel<<<g2, 256>>>();

    final_kernel<<<BATCH, 256>>>(out);
}

// round 4
// speedup vs baseline: 1.0281x; 1.0281x over previous
#include <cuda_runtime.h>
#include <cuda_bf16.h>

#define BATCH 128
#define NANCH 8732
#define NCLS  21
#define KTOP  200
#define CONF_T 0.01f
#define NMS_T  0.45f
#define NMSW 7                            // ceil(224/32) mask words per row

// ---------------- scratch (device globals; no allocations allowed) ----------
__device__ float4 g_boxes[BATCH * NANCH];                       // ~17.9 MB
__device__ float  g_probs[(size_t)BATCH * 20 * NANCH];          // ~89.4 MB
__device__ float  g_sc[BATCH * 20 * KTOP];                      // kept scores
__device__ float4 g_sb[BATCH * 20 * KTOP];                      // kept boxes

// ---------------- kernel 1: decode + softmax ---------------------------------
__global__ void prep_kernel(const float* __restrict__ loc,
                            const float* __restrict__ conf,
                            const float* __restrict__ dbox) {
    __shared__ float sc[128 * NCLS];
    int b   = blockIdx.y;
    int n0  = blockIdx.x * 128;
    int tid = threadIdx.x;              // 128 threads
    int nrows = NANCH - n0; if (nrows > 128) nrows = 128;

    const float* cp = conf + ((size_t)b * NANCH + n0) * NCLS;
    for (int i = tid; i < nrows * NCLS; i += 128) sc[i] = cp[i];
    __syncthreads();

    if (tid < nrows) {
        int n = n0 + tid;
        const float* x = &sc[tid * NCLS];
        float m = x[0];
#pragma unroll
        for (int c = 1; c < NCLS; c++) m = fmaxf(m, x[c]);
        float e[NCLS];
        float s = 0.f;
#pragma unroll
        for (int c = 0; c < NCLS; c++) { e[c] = expf(x[c] - m); s += e[c]; }

        // decode box
        float4 l = reinterpret_cast<const float4*>(loc)[(size_t)b * NANCH + n];
        float4 d = reinterpret_cast<const float4*>(dbox)[n];
        float cx = d.x + l.x * 0.1f * d.z;
        float cy = d.y + l.y * 0.1f * d.w;
        float w  = d.z * expf(l.z * 0.2f);
        float h  = d.w * expf(l.w * 0.2f);
        float x1 = cx - w * 0.5f;
        float y1 = cy - h * 0.5f;
        float x2 = x1 + w;
        float y2 = y1 + h;
        x1 = fminf(fmaxf(x1, 0.f), 1.f);
        y1 = fminf(fmaxf(y1, 0.f), 1.f);
        x2 = fminf(fmaxf(x2, 0.f), 1.f);
        y2 = fminf(fmaxf(y2, 0.f), 1.f);
        g_boxes[(size_t)b * NANCH + n] = make_float4(x1, y1, x2, y2);

        // class-major probs (skip background class 0); coalesced per-c row
#pragma unroll
        for (int c = 1; c < NCLS; c++)
            g_probs[((size_t)b * 20 + (c - 1)) * NANCH + n] = e[c] / s;
    }
}

// ---------------- shared helpers ---------------------------------------------
__device__ __forceinline__ unsigned warp_suffix_incl(unsigned x) {
    unsigned lane = threadIdx.x & 31;
#pragma unroll
    for (int d = 1; d < 32; d <<= 1) {
        unsigned t = __shfl_down_sync(0xffffffffu, x, d);
        if (lane + d < 32) x += t;
    }
    return x;   // sum of x over lanes [lane..31]
}

// exclusive suffix over 256 threads: sum of x over threads with tid' > tid
__device__ __forceinline__ unsigned block_excl_suffix_256(unsigned x, unsigned* s_warp) {
    int lane = threadIdx.x & 31, wid = threadIdx.x >> 5;
    unsigned inc = warp_suffix_incl(x);
    if (lane == 0) s_warp[wid] = inc;
    __syncthreads();
    unsigned above = 0;
#pragma unroll
    for (int w = 0; w < 8; w++) if (w > wid) above += s_warp[w];
    return (inc - x) + above;
}

// bitonic sort of 256 u64 keys, descending; one element per thread (blockDim=256).
// sub-warp stages use shfl; cross-warp stages use the provided 256-slot scratch.
__device__ __forceinline__ unsigned long long bitonic256_desc(
        unsigned long long v, unsigned long long* sh) {
    int tid = threadIdx.x;
#pragma unroll
    for (int kk = 2; kk <= 256; kk <<= 1) {
        for (int j = kk >> 1; j > 0; j >>= 1) {
            unsigned long long w;
            if (j >= 32) {
                __syncthreads();
                sh[tid] = v;
                __syncthreads();
                w = sh[tid ^ j];
            } else {
                w = __shfl_xor_sync(0xffffffffu, v, j);
            }
            bool keepMax = ((tid & j) == 0) == ((tid & kk) == 0);
            if (keepMax ? (w > v) : (w < v)) v = w;
        }
    }
    return v;
}

// ---------------- kernel 2: per-(batch,class) top-200 + greedy NMS -----------
// All valid scores s satisfy 0.01 < s <= 1  =>  float bits have bit31=0 and
// bits[30:26] = 01111. Only bits[25:0] vary: 3 radix rounds (10+8+8 bits).
__global__ __launch_bounds__(256) void nms_kernel() {
    __shared__ union { unsigned hist[1024]; unsigned mask[KTOP * NMSW]; } su;
    __shared__ unsigned long long cand[256];
    __shared__ float4 sbox[KTOP];
    __shared__ float  sarea[KTOP];
    __shared__ unsigned s_warp[8];
    __shared__ unsigned s_alivew[8];
    __shared__ int selBin, selKk;
    __shared__ unsigned s_total, s_cnt;

    int c    = blockIdx.x;               // 0..19 -> class c+1
    int b    = blockIdx.y;
    int tid  = threadIdx.x;              // 256 threads
    int lane = tid & 31, wid = tid >> 5;
    const float* __restrict__ row = g_probs + ((size_t)b * 20 + c) * NANCH;

    for (int i = tid; i < 1024; i += 256) su.hist[i] = 0;
    __syncthreads();

    // pass A: threshold + histogram bits[25:16] (row stays L2-resident)
    for (int n = tid; n < NANCH; n += 256) {
        float s = row[n];
        if (s > CONF_T) atomicAdd(&su.hist[(__float_as_uint(s) >> 16) & 1023u], 1u);
    }
    __syncthreads();

    {   // parallel suffix selection over 1024 bins (4 bins/thread)
        unsigned h0 = su.hist[4*tid], h1 = su.hist[4*tid+1];
        unsigned h2 = su.hist[4*tid+2], h3 = su.hist[4*tid+3];
        unsigned s3 = h3, s2 = h2 + s3, s1 = h1 + s2, s0 = h0 + s1;
        unsigned E = block_excl_suffix_256(s0, s_warp);
        if (tid == 0) s_total = s0 + E;
        unsigned f0 = s0+E, f1 = s1+E, f2 = s2+E, f3 = s3+E, f4 = E;
        if (f0 >= KTOP && f1 < KTOP) { selBin = 4*tid+0; selKk = KTOP - (int)f1; }
        if (f1 >= KTOP && f2 < KTOP) { selBin = 4*tid+1; selKk = KTOP - (int)f2; }
        if (f2 >= KTOP && f3 < KTOP) { selBin = 4*tid+2; selKk = KTOP - (int)f3; }
        if (f3 >= KTOP && f4 < KTOP) { selBin = 4*tid+3; selKk = KTOP - (int)f4; }
    }
    __syncthreads();

    unsigned pivot = 1u;                 // total<=200 -> take every key
    if (s_total > KTOP) {                // uniform branch
        int d0 = selBin, kk1 = selKk;
        su.hist[tid] = 0;
        __syncthreads();
        // round 1: bits[15:8] within prefix d0
        for (int n = tid; n < NANCH; n += 256) {
            float s = row[n];
            if (s > CONF_T) {
                unsigned k = __float_as_uint(s);
                if (((k >> 16) & 1023u) == (unsigned)d0)
                    atomicAdd(&su.hist[(k >> 8) & 255u], 1u);
            }
        }
        __syncthreads();
        {
            unsigned h = su.hist[tid];
            unsigned E = block_excl_suffix_256(h, s_warp);
            if (h + E >= (unsigned)kk1 && E < (unsigned)kk1) { selBin = tid; selKk = kk1 - (int)E; }
        }
        __syncthreads();
        int d1 = selBin, kk2 = selKk;
        unsigned pref = ((unsigned)d0 << 8) | (unsigned)d1;   // bits[25:8]
        su.hist[tid] = 0;
        __syncthreads();
        // round 2: bits[7:0] within prefix (d0,d1)
        for (int n = tid; n < NANCH; n += 256) {
            float s = row[n];
            if (s > CONF_T) {
                unsigned k = __float_as_uint(s);
                if (((k >> 8) & 0x3FFFFu) == pref)
                    atomicAdd(&su.hist[k & 255u], 1u);
            }
        }
        __syncthreads();
        {
            unsigned h = su.hist[tid];
            unsigned E = block_excl_suffix_256(h, s_warp);
            if (h + E >= (unsigned)kk2 && E < (unsigned)kk2) { selBin = tid; }
        }
        __syncthreads();
        // exact key of the 200th largest score
        pivot = (15u << 26) | ((unsigned)d0 << 16) | ((unsigned)d1 << 8) | (unsigned)selBin;
    }

    if (tid == 0) s_cnt = 0;
    __syncthreads();

    // collect candidates (>= pivot); 64-bit key = (scorebits, ~index) for
    // stable descending order identical to jax.lax.top_k
    for (int n = tid; n < NANCH; n += 256) {
        float s = row[n];
        if (s > CONF_T) {
            unsigned k = __float_as_uint(s);
            if (k >= pivot) {
                unsigned p = atomicAdd(&s_cnt, 1u);
                if (p < 256u) cand[p] = ((unsigned long long)k << 32) | (unsigned)(~n);
            }
        }
    }
    __syncthreads();
    unsigned mcnt = s_cnt < 256u ? s_cnt : 256u;
    unsigned long long v = (tid < (int)mcnt) ? cand[tid] : 0ull;
    v = bitonic256_desc(v, cand);
    __syncthreads();              // all scratch reads done before overwrite
    cand[tid] = v;
    __syncthreads();

    // ---- NMS setup: top-200 boxes into shared, own slot in registers ----
    bool   myAlive = false;
    float4 myBox   = make_float4(0.f, 0.f, 0.f, 0.f);
    float  myScore = 0.f;
    if (tid < KTOP) {
        float area = 0.f;
        unsigned long long vv = cand[tid];
        if (vv) {
            unsigned n = ~(unsigned)(vv & 0xFFFFFFFFu);
            myBox   = g_boxes[(size_t)b * NANCH + n];
            area    = (myBox.z - myBox.x) * (myBox.w - myBox.y);
            myScore = __uint_as_float((unsigned)(vv >> 32));
            myAlive = true;
        }
        sbox[tid]  = myBox;
        sarea[tid] = area;
    }
    // initial alive bitmap (bits >= 200 are 0)
    {
        unsigned ball = __ballot_sync(0xffffffffu, tid < KTOP && myAlive);
        if (lane == 0) s_alivew[wid] = (wid < NMSW) ? ball : 0u;
    }
    __syncthreads();

    int nrow = (int)(mcnt < (unsigned)KTOP ? mcnt : (unsigned)KTOP);

    // ---- suppression matrix: mask[i][w] bit l = suppress j=w*32+l (j>i) ----
    // Barrier-free: 8 warps cover nrow*NMSW row-words, one IoU per lane.
    for (int p = wid; p < nrow * NMSW; p += 8) {
        int i = p / NMSW, w = p - i * NMSW;
        int j = w * 32 + lane;
        bool sup = false;
        if (j > i && j < nrow) {
            float4 bi = sbox[i];
            float4 bj = sbox[j];
            float xx1 = fmaxf(bj.x, bi.x), yy1 = fmaxf(bj.y, bi.y);
            float xx2 = fminf(bj.z, bi.z), yy2 = fminf(bj.w, bi.w);
            float inter = fmaxf(xx2 - xx1, 0.f) * fmaxf(yy2 - yy1, 0.f);
            float iou = inter / (sarea[j] + sarea[i] - inter);
            sup = !(iou <= NMS_T);       // NaN -> suppress (torch semantics)
        }
        unsigned m = __ballot_sync(0xffffffffu, sup);
        if (lane == 0) su.mask[p] = m;
    }
    __syncthreads();

    // ---- greedy scan (warp 0, registers only, no block barriers) ----
    if (wid == 0) {
        unsigned aw = (lane < NMSW) ? s_alivew[lane] : 0u;
        for (int i = 0; i < nrow; i++) {
            unsigned wbits = __shfl_sync(0xffffffffu, aw, i >> 5);
            if ((wbits >> (i & 31)) & 1u) {           // i survives -> apply row
                unsigned m = (lane < NMSW) ? su.mask[i * NMSW + lane] : 0u;
                aw &= ~m;
            }
        }
        if (lane < NMSW) s_alivew[lane] = aw;
    }
    __syncthreads();

    if (tid < KTOP) {
        bool kept = myAlive && ((s_alivew[tid >> 5] >> (tid & 31)) & 1u);
        int o = (b * 20 + c) * KTOP + tid;
        g_sc[o] = kept ? myScore : 0.f;
        g_sb[o] = kept ? myBox : make_float4(0.f, 0.f, 0.f, 0.f);
    }
}

// ---------------- kernel 3: global top-200 + per-class compaction ------------
__global__ __launch_bounds__(256) void final_kernel(float* __restrict__ out) {
    __shared__ unsigned hist[1024];
    __shared__ unsigned long long cand[256];
    __shared__ unsigned s_warp[8];
    __shared__ int selBin, selKk;
    __shared__ unsigned s_total, s_cnt;

    int b   = blockIdx.x;
    int tid = threadIdx.x;              // 256 threads
    const float* __restrict__ sc = g_sc + b * 4000;

    for (int i = tid; i < 1024; i += 256) hist[i] = 0;
    __syncthreads();
    for (int n = tid; n < 4000; n += 256) {
        float s = sc[n];                // kept scores are 0 or > 0.01
        if (s > 0.f) atomicAdd(&hist[(__float_as_uint(s) >> 16) & 1023u], 1u);
    }
    __syncthreads();
    {
        unsigned h0 = hist[4*tid], h1 = hist[4*tid+1], h2 = hist[4*tid+2], h3 = hist[4*tid+3];
        unsigned s3 = h3, s2 = h2 + s3, s1 = h1 + s2, s0 = h0 + s1;
        unsigned E = block_excl_suffix_256(s0, s_warp);
        if (tid == 0) s_total = s0 + E;
        unsigned f0 = s0+E, f1 = s1+E, f2 = s2+E, f3 = s3+E, f4 = E;
        if (f0 >= KTOP && f1 < KTOP) { selBin = 4*tid+0; selKk = KTOP - (int)f1; }
        if (f1 >= KTOP && f2 < KTOP) { selBin = 4*tid+1; selKk = KTOP - (int)f2; }
        if (f2 >= KTOP && f3 < KTOP) { selBin = 4*tid+2; selKk = KTOP - (int)f3; }
        if (f3 >= KTOP && f4 < KTOP) { selBin = 4*tid+3; selKk = KTOP - (int)f4; }
    }
    __syncthreads();

    unsigned pivot = 1u;
    if (s_total > KTOP) {
        int d0 = selBin, kk1 = selKk;
        hist[tid] = 0;
        __syncthreads();
        for (int n = tid; n < 4000; n += 256) {
            float s = sc[n];
            if (s > 0.f) {
                unsigned k = __float_as_uint(s);
                if (((k >> 16) & 1023u) == (unsigned)d0)
                    atomicAdd(&hist[(k >> 8) & 255u], 1u);
            }
        }
        __syncthreads();
        {
            unsigned h = hist[tid];
            unsigned E = block_excl_suffix_256(h, s_warp);
            if (h + E >= (unsigned)kk1 && E < (unsigned)kk1) { selBin = tid; selKk = kk1 - (int)E; }
        }
        __syncthreads();
        int d1 = selBin, kk2 = selKk;
        unsigned pref = ((unsigned)d0 << 8) | (unsigned)d1;
        hist[tid] = 0;
        __syncthreads();
        for (int n = tid; n < 4000; n += 256) {
            float s = sc[n];
            if (s > 0.f) {
                unsigned k = __float_as_uint(s);
                if (((k >> 8) & 0x3FFFFu) == pref)
                    atomicAdd(&hist[k & 255u], 1u);
            }
        }
        __syncthreads();
        {
            unsigned h = hist[tid];
            unsigned E = block_excl_suffix_256(h, s_warp);
            if (h + E >= (unsigned)kk2 && E < (unsigned)kk2) { selBin = tid; }
        }
        __syncthreads();
        pivot = (15u << 26) | ((unsigned)d0 << 16) | ((unsigned)d1 << 8) | (unsigned)selBin;
    }

    if (tid == 0) s_cnt = 0;
    __syncthreads();
    for (int n = tid; n < 4000; n += 256) {
        float s = sc[n];
        if (s > 0.f) {
            unsigned k = __float_as_uint(s);
            if (k >= pivot) {
                unsigned p = atomicAdd(&s_cnt, 1u);
                if (p < 256u) cand[p] = ((unsigned long long)k << 32) | (unsigned)(~n);
            }
        }
    }
    __syncthreads();
    unsigned mcnt = s_cnt < 256u ? s_cnt : 256u;
    unsigned long long v = (tid < (int)mcnt) ? cand[tid] : 0ull;
    v = bitonic256_desc(v, cand);
    __syncthreads();
    cand[tid] = v;
    __syncthreads();

    // zero the whole batch output (poisoned by harness), then compact
    float* o = out + (size_t)b * NCLS * KTOP * 5;
    for (int i = tid; i < NCLS * KTOP * 5; i += 256) o[i] = 0.f;
    __syncthreads();

    if (tid < 20) {
        int cnt = 0;
        for (int k = 0; k < KTOP; k++) {            // global top-200 only
            unsigned long long vv = cand[k];
            if (!vv) break;                          // zeros sort last
            unsigned idx = ~(unsigned)(vv & 0xFFFFFFFFu);
            if ((int)(idx / KTOP) == tid) {          // class tid+1
                float s = __uint_as_float((unsigned)(vv >> 32));
                float4 bx = g_sb[b * 4000 + idx];
                float* dst = o + ((size_t)(tid + 1) * KTOP + cnt) * 5;
                dst[0] = s;
                dst[1] = bx.x; dst[2] = bx.y; dst[3] = bx.z; dst[4] = bx.w;
                cnt++;
            }
        }
    }
}

// ---------------- launch ------------------------------------------------------
extern "C" void kernel_launch(void* const* d_in, const int* in_sizes, int n_in,
                              void* d_out, int out_size) {
    const float* loc  = (const float*)d_in[0];   // [128, 8732, 4]
    const float* conf = (const float*)d_in[1];   // [128, 8732, 21]
    const float* dbox = (const float*)d_in[2];   // [8732, 4]
    float* out = (float*)d_out;                  // [128, 21, 200, 5]

    dim3 g1((NANCH + 127) / 128, BATCH);
    prep_kernel<<<g1, 128>>>(loc, conf, dbox);

    dim3 g2(20, BATCH);
    nms_kernel<<<g2, 256>>>();

    final_kernel<<<BATCH, 256>>>(out);
}

// round 5
// speedup vs baseline: 1.2694x; 1.2347x over previous
#include <cuda_runtime.h>
#include <cuda_bf16.h>

#define BATCH 128
#define NANCH 8732
#define NCLS  21
#define KTOP  200
#define CONF_T 0.01f
#define NMS_T  0.45f
#define NMSW 7                            // ceil(224/32) alive words

// ---------------- scratch (device globals; no allocations allowed) ----------
__device__ float4 g_boxes[BATCH * NANCH];                       // ~17.9 MB
__device__ float  g_probs[(size_t)BATCH * 20 * NANCH];          // ~89.4 MB
__device__ float  g_sc[BATCH * 20 * KTOP];                      // kept scores
__device__ float4 g_sb[BATCH * 20 * KTOP];                      // kept boxes

// ---------------- kernel 1: decode + softmax ---------------------------------
__global__ void prep_kernel(const float* __restrict__ loc,
                            const float* __restrict__ conf,
                            const float* __restrict__ dbox) {
    __shared__ float sc[128 * NCLS];
    int b   = blockIdx.y;
    int n0  = blockIdx.x * 128;
    int tid = threadIdx.x;              // 128 threads
    int nrows = NANCH - n0; if (nrows > 128) nrows = 128;

    const float* cp = conf + ((size_t)b * NANCH + n0) * NCLS;
    for (int i = tid; i < nrows * NCLS; i += 128) sc[i] = cp[i];
    __syncthreads();

    if (tid < nrows) {
        int n = n0 + tid;
        const float* x = &sc[tid * NCLS];
        float m = x[0];
#pragma unroll
        for (int c = 1; c < NCLS; c++) m = fmaxf(m, x[c]);
        float e[NCLS];
        float s = 0.f;
#pragma unroll
        for (int c = 0; c < NCLS; c++) { e[c] = expf(x[c] - m); s += e[c]; }

        // decode box
        float4 l = reinterpret_cast<const float4*>(loc)[(size_t)b * NANCH + n];
        float4 d = reinterpret_cast<const float4*>(dbox)[n];
        float cx = d.x + l.x * 0.1f * d.z;
        float cy = d.y + l.y * 0.1f * d.w;
        float w  = d.z * expf(l.z * 0.2f);
        float h  = d.w * expf(l.w * 0.2f);
        float x1 = cx - w * 0.5f;
        float y1 = cy - h * 0.5f;
        float x2 = x1 + w;
        float y2 = y1 + h;
        x1 = fminf(fmaxf(x1, 0.f), 1.f);
        y1 = fminf(fmaxf(y1, 0.f), 1.f);
        x2 = fminf(fmaxf(x2, 0.f), 1.f);
        y2 = fminf(fmaxf(y2, 0.f), 1.f);
        g_boxes[(size_t)b * NANCH + n] = make_float4(x1, y1, x2, y2);

        // class-major probs (skip background class 0); coalesced per-c row
#pragma unroll
        for (int c = 1; c < NCLS; c++)
            g_probs[((size_t)b * 20 + (c - 1)) * NANCH + n] = e[c] / s;
    }
}

// ---------------- shared helpers ---------------------------------------------
__device__ __forceinline__ unsigned warp_suffix_incl(unsigned x) {
    unsigned lane = threadIdx.x & 31;
#pragma unroll
    for (int d = 1; d < 32; d <<= 1) {
        unsigned t = __shfl_down_sync(0xffffffffu, x, d);
        if (lane + d < 32) x += t;
    }
    return x;   // sum of x over lanes [lane..31]
}

// exclusive suffix over 256 threads: sum of x over threads with tid' > tid
__device__ __forceinline__ unsigned block_excl_suffix_256(unsigned x, unsigned* s_warp) {
    int lane = threadIdx.x & 31, wid = threadIdx.x >> 5;
    unsigned inc = warp_suffix_incl(x);
    if (lane == 0) s_warp[wid] = inc;
    __syncthreads();
    unsigned above = 0;
#pragma unroll
    for (int w = 0; w < 8; w++) if (w > wid) above += s_warp[w];
    return (inc - x) + above;
}

// bitonic sort of 256 u64 keys, descending; one element per thread (blockDim=256).
// sub-warp stages use shfl; cross-warp stages use the provided 256-slot scratch.
__device__ __forceinline__ unsigned long long bitonic256_desc(
        unsigned long long v, unsigned long long* sh) {
    int tid = threadIdx.x;
#pragma unroll
    for (int kk = 2; kk <= 256; kk <<= 1) {
        for (int j = kk >> 1; j > 0; j >>= 1) {
            unsigned long long w;
            if (j >= 32) {
                __syncthreads();
                sh[tid] = v;
                __syncthreads();
                w = sh[tid ^ j];
            } else {
                w = __shfl_xor_sync(0xffffffffu, v, j);
            }
            bool keepMax = ((tid & j) == 0) == ((tid & kk) == 0);
            if (keepMax ? (w > v) : (w < v)) v = w;
        }
    }
    return v;
}

// ---------------- kernel 2: per-(batch,class) top-200 + greedy NMS -----------
// All valid scores s satisfy 0.01 < s <= 1  =>  float bits have bit31=0 and
// bits[30:26] = 01111. Only bits[25:0] vary: 3 radix rounds (10+8+8 bits).
__global__ __launch_bounds__(256) void nms_kernel() {
    __shared__ unsigned hist[1024];
    __shared__ unsigned long long cand[256];
    __shared__ float4 sbox[224];        // padded so chunk 6 lanes stay in-bounds
    __shared__ float  sarea[224];
    __shared__ unsigned s_warp[8];
    __shared__ unsigned s_alivew[NMSW];
    __shared__ int selBin, selKk;
    __shared__ unsigned s_total, s_cnt;

    int c    = blockIdx.x;               // 0..19 -> class c+1
    int b    = blockIdx.y;
    int tid  = threadIdx.x;              // 256 threads
    int lane = tid & 31, wid = tid >> 5;
    const float* __restrict__ row = g_probs + ((size_t)b * 20 + c) * NANCH;

    for (int i = tid; i < 1024; i += 256) hist[i] = 0;
    __syncthreads();

    // pass A: threshold + histogram bits[25:16] (row stays L2-resident)
    for (int n = tid; n < NANCH; n += 256) {
        float s = row[n];
        if (s > CONF_T) atomicAdd(&hist[(__float_as_uint(s) >> 16) & 1023u], 1u);
    }
    __syncthreads();

    {   // parallel suffix selection over 1024 bins (4 bins/thread)
        unsigned h0 = hist[4*tid], h1 = hist[4*tid+1];
        unsigned h2 = hist[4*tid+2], h3 = hist[4*tid+3];
        unsigned s3 = h3, s2 = h2 + s3, s1 = h1 + s2, s0 = h0 + s1;
        unsigned E = block_excl_suffix_256(s0, s_warp);
        if (tid == 0) s_total = s0 + E;
        unsigned f0 = s0+E, f1 = s1+E, f2 = s2+E, f3 = s3+E, f4 = E;
        if (f0 >= KTOP && f1 < KTOP) { selBin = 4*tid+0; selKk = KTOP - (int)f1; }
        if (f1 >= KTOP && f2 < KTOP) { selBin = 4*tid+1; selKk = KTOP - (int)f2; }
        if (f2 >= KTOP && f3 < KTOP) { selBin = 4*tid+2; selKk = KTOP - (int)f3; }
        if (f3 >= KTOP && f4 < KTOP) { selBin = 4*tid+3; selKk = KTOP - (int)f4; }
    }
    __syncthreads();

    unsigned pivot = 1u;                 // total<=200 -> take every key
    if (s_total > KTOP) {                // uniform branch
        int d0 = selBin, kk1 = selKk;
        hist[tid] = 0;
        __syncthreads();
        // round 1: bits[15:8] within prefix d0
        for (int n = tid; n < NANCH; n += 256) {
            float s = row[n];
            if (s > CONF_T) {
                unsigned k = __float_as_uint(s);
                if (((k >> 16) & 1023u) == (unsigned)d0)
                    atomicAdd(&hist[(k >> 8) & 255u], 1u);
            }
        }
        __syncthreads();
        {
            unsigned h = hist[tid];
            unsigned E = block_excl_suffix_256(h, s_warp);
            if (h + E >= (unsigned)kk1 && E < (unsigned)kk1) { selBin = tid; selKk = kk1 - (int)E; }
        }
        __syncthreads();
        int d1 = selBin, kk2 = selKk;
        unsigned pref = ((unsigned)d0 << 8) | (unsigned)d1;   // bits[25:8]
        hist[tid] = 0;
        __syncthreads();
        // round 2: bits[7:0] within prefix (d0,d1)
        for (int n = tid; n < NANCH; n += 256) {
            float s = row[n];
            if (s > CONF_T) {
                unsigned k = __float_as_uint(s);
                if (((k >> 8) & 0x3FFFFu) == pref)
                    atomicAdd(&hist[k & 255u], 1u);
            }
        }
        __syncthreads();
        {
            unsigned h = hist[tid];
            unsigned E = block_excl_suffix_256(h, s_warp);
            if (h + E >= (unsigned)kk2 && E < (unsigned)kk2) { selBin = tid; }
        }
        __syncthreads();
        // exact key of the 200th largest score
        pivot = (15u << 26) | ((unsigned)d0 << 16) | ((unsigned)d1 << 8) | (unsigned)selBin;
    }

    if (tid == 0) s_cnt = 0;
    __syncthreads();

    // collect candidates (>= pivot); 64-bit key = (scorebits, ~index) for
    // stable descending order identical to jax.lax.top_k
    for (int n = tid; n < NANCH; n += 256) {
        float s = row[n];
        if (s > CONF_T) {
            unsigned k = __float_as_uint(s);
            if (k >= pivot) {
                unsigned p = atomicAdd(&s_cnt, 1u);
                if (p < 256u) cand[p] = ((unsigned long long)k << 32) | (unsigned)(~n);
            }
        }
    }
    __syncthreads();
    unsigned mcnt = s_cnt < 256u ? s_cnt : 256u;
    unsigned long long v = (tid < (int)mcnt) ? cand[tid] : 0ull;
    v = bitonic256_desc(v, cand);
    __syncthreads();              // all scratch reads done before overwrite
    cand[tid] = v;
    __syncthreads();

    // ---- NMS setup: top-200 boxes into shared (padded to 224) ----
    bool   myAlive = false;
    float4 myBox   = make_float4(0.f, 0.f, 0.f, 0.f);
    float  myArea  = 0.f;
    float  myScore = 0.f;
    if (tid < 224) {
        if (tid < KTOP) {
            unsigned long long vv = cand[tid];
            if (vv) {
                unsigned n = ~(unsigned)(vv & 0xFFFFFFFFu);
                myBox   = g_boxes[(size_t)b * NANCH + n];
                myArea  = (myBox.z - myBox.x) * (myBox.w - myBox.y);
                myScore = __uint_as_float((unsigned)(vv >> 32));
                myAlive = true;
            }
        }
        sbox[tid]  = myBox;
        sarea[tid] = myArea;
    }
    {
        unsigned ball = __ballot_sync(0xffffffffu, tid < KTOP && myAlive);
        if (lane == 0 && wid < NMSW) s_alivew[wid] = ball;
    }
    __syncthreads();

    // ---- blocked greedy NMS: 7 chunks x 32, 2 barriers per chunk ----
    // Exactly the sequential greedy: a candidate is suppressed iff some
    // earlier SURVIVOR overlaps it (IoU not <= thresh; NaN suppresses).
    for (int c0 = 0; c0 < KTOP; c0 += 32) {
        int cw = c0 >> 5;
        // intra-chunk: warp 0 resolves bits [c0, c0+32) serially
        if (wid == 0) {
            unsigned aliveW = s_alivew[cw];
            float4 bl = sbox[c0 + lane];
            float  al = sarea[c0 + lane];
            for (int bb = 0; bb < 32; bb++) {
                if ((aliveW >> bb) & 1u) {            // alive-at-turn only
                    float4 bi = sbox[c0 + bb];         // uniform broadcast
                    float  ai = sarea[c0 + bb];
                    float xx1 = fmaxf(bl.x, bi.x), yy1 = fmaxf(bl.y, bi.y);
                    float xx2 = fminf(bl.z, bi.z), yy2 = fminf(bl.w, bi.w);
                    float inter = fmaxf(xx2 - xx1, 0.f) * fmaxf(yy2 - yy1, 0.f);
                    float iou = inter / (al + ai - inter);
                    bool sup = (lane > bb) && !(iou <= NMS_T);  // NaN -> suppress
                    aliveW &= ~__ballot_sync(0xffffffffu, sup);
                }
            }
            if (lane == 0) s_alivew[cw] = aliveW;
        }
        __syncthreads();
        // cross-chunk: later candidates test against this chunk's survivors
        unsigned ca = s_alivew[cw];
        if (myAlive && tid >= c0 + 32 && tid < KTOP) {
            unsigned m = ca;
            bool killed = false;
            while (m) {
                int bb = __ffs(m) - 1; m &= m - 1;
                float4 bi = sbox[c0 + bb];
                float  ai = sarea[c0 + bb];
                float xx1 = fmaxf(myBox.x, bi.x), yy1 = fmaxf(myBox.y, bi.y);
                float xx2 = fminf(myBox.z, bi.z), yy2 = fminf(myBox.w, bi.w);
                float inter = fmaxf(xx2 - xx1, 0.f) * fmaxf(yy2 - yy1, 0.f);
                float iou = inter / (myArea + ai - inter);
                if (!(iou <= NMS_T)) { killed = true; break; }
            }
            if (killed) {
                myAlive = false;
                atomicAnd(&s_alivew[tid >> 5], ~(1u << (tid & 31)));
            }
        }
        __syncthreads();
    }

    if (tid < KTOP) {
        bool kept = (s_alivew[tid >> 5] >> (tid & 31)) & 1u;
        int o = (b * 20 + c) * KTOP + tid;
        g_sc[o] = kept ? myScore : 0.f;
        g_sb[o] = kept ? myBox : make_float4(0.f, 0.f, 0.f, 0.f);
    }
}

// ---------------- kernel 3: global top-200 + per-class compaction ------------
__global__ __launch_bounds__(256) void final_kernel(float* __restrict__ out) {
    __shared__ unsigned hist[1024];
    __shared__ unsigned long long cand[256];
    __shared__ unsigned s_warp[8];
    __shared__ int selBin, selKk;
    __shared__ unsigned s_total, s_cnt;

    int b   = blockIdx.x;
    int tid = threadIdx.x;              // 256 threads
    const float* __restrict__ sc = g_sc + b * 4000;

    for (int i = tid; i < 1024; i += 256) hist[i] = 0;
    __syncthreads();
    for (int n = tid; n < 4000; n += 256) {
        float s = sc[n];                // kept scores are 0 or > 0.01
        if (s > 0.f) atomicAdd(&hist[(__float_as_uint(s) >> 16) & 1023u], 1u);
    }
    __syncthreads();
    {
        unsigned h0 = hist[4*tid], h1 = hist[4*tid+1], h2 = hist[4*tid+2], h3 = hist[4*tid+3];
        unsigned s3 = h3, s2 = h2 + s3, s1 = h1 + s2, s0 = h0 + s1;
        unsigned E = block_excl_suffix_256(s0, s_warp);
        if (tid == 0) s_total = s0 + E;
        unsigned f0 = s0+E, f1 = s1+E, f2 = s2+E, f3 = s3+E, f4 = E;
        if (f0 >= KTOP && f1 < KTOP) { selBin = 4*tid+0; selKk = KTOP - (int)f1; }
        if (f1 >= KTOP && f2 < KTOP) { selBin = 4*tid+1; selKk = KTOP - (int)f2; }
        if (f2 >= KTOP && f3 < KTOP) { selBin = 4*tid+2; selKk = KTOP - (int)f3; }
        if (f3 >= KTOP && f4 < KTOP) { selBin = 4*tid+3; selKk = KTOP - (int)f4; }
    }
    __syncthreads();

    unsigned pivot = 1u;
    if (s_total > KTOP) {
        int d0 = selBin, kk1 = selKk;
        hist[tid] = 0;
        __syncthreads();
        for (int n = tid; n < 4000; n += 256) {
            float s = sc[n];
            if (s > 0.f) {
                unsigned k = __float_as_uint(s);
                if (((k >> 16) & 1023u) == (unsigned)d0)
                    atomicAdd(&hist[(k >> 8) & 255u], 1u);
            }
        }
        __syncthreads();
        {
            unsigned h = hist[tid];
            unsigned E = block_excl_suffix_256(h, s_warp);
            if (h + E >= (unsigned)kk1 && E < (unsigned)kk1) { selBin = tid; selKk = kk1 - (int)E; }
        }
        __syncthreads();
        int d1 = selBin, kk2 = selKk;
        unsigned pref = ((unsigned)d0 << 8) | (unsigned)d1;
        hist[tid] = 0;
        __syncthreads();
        for (int n = tid; n < 4000; n += 256) {
            float s = sc[n];
            if (s > 0.f) {
                unsigned k = __float_as_uint(s);
                if (((k >> 8) & 0x3FFFFu) == pref)
                    atomicAdd(&hist[k & 255u], 1u);
            }
        }
        __syncthreads();
        {
            unsigned h = hist[tid];
            unsigned E = block_excl_suffix_256(h, s_warp);
            if (h + E >= (unsigned)kk2 && E < (unsigned)kk2) { selBin = tid; }
        }
        __syncthreads();
        pivot = (15u << 26) | ((unsigned)d0 << 16) | ((unsigned)d1 << 8) | (unsigned)selBin;
    }

    if (tid == 0) s_cnt = 0;
    __syncthreads();
    for (int n = tid; n < 4000; n += 256) {
        float s = sc[n];
        if (s > 0.f) {
            unsigned k = __float_as_uint(s);
            if (k >= pivot) {
                unsigned p = atomicAdd(&s_cnt, 1u);
                if (p < 256u) cand[p] = ((unsigned long long)k << 32) | (unsigned)(~n);
            }
        }
    }
    __syncthreads();
    unsigned mcnt = s_cnt < 256u ? s_cnt : 256u;
    unsigned long long v = (tid < (int)mcnt) ? cand[tid] : 0ull;
    v = bitonic256_desc(v, cand);
    __syncthreads();
    cand[tid] = v;
    __syncthreads();

    // zero the whole batch output (poisoned by harness), then compact
    float* o = out + (size_t)b * NCLS * KTOP * 5;
    for (int i = tid; i < NCLS * KTOP * 5; i += 256) o[i] = 0.f;
    __syncthreads();

    if (tid < 20) {
        int cnt = 0;
        for (int k = 0; k < KTOP; k++) {            // global top-200 only
            unsigned long long vv = cand[k];
            if (!vv) break;                          // zeros sort last
            unsigned idx = ~(unsigned)(vv & 0xFFFFFFFFu);
            if ((int)(idx / KTOP) == tid) {          // class tid+1
                float s = __uint_as_float((unsigned)(vv >> 32));
                float4 bx = g_sb[b * 4000 + idx];
                float* dst = o + ((size_t)(tid + 1) * KTOP + cnt) * 5;
                dst[0] = s;
                dst[1] = bx.x; dst[2] = bx.y; dst[3] = bx.z; dst[4] = bx.w;
                cnt++;
            }
        }
    }
}

// ---------------- launch ------------------------------------------------------
extern "C" void kernel_launch(void* const* d_in, const int* in_sizes, int n_in,
                              void* d_out, int out_size) {
    const float* loc  = (const float*)d_in[0];   // [128, 8732, 4]
    const float* conf = (const float*)d_in[1];   // [128, 8732, 21]
    const float* dbox = (const float*)d_in[2];   // [8732, 4]
    float* out = (float*)d_out;                  // [128, 21, 200, 5]

    dim3 g1((NANCH + 127) / 128, BATCH);
    prep_kernel<<<g1, 128>>>(loc, conf, dbox);

    dim3 g2(20, BATCH);
    nms_kernel<<<g2, 256>>>();

    final_kernel<<<BATCH, 256>>>(out);
}

// round 8
// speedup vs baseline: 1.4786x; 1.1648x over previous
#include <cuda_runtime.h>
#include <cuda_bf16.h>

#define BATCH 128
#define NANCH 8732
#define NCLS  21
#define KTOP  200
#define CONF_T 0.01f
#define NMS_T  0.45f

// ---------------- scratch (device globals; no allocations allowed) ----------
__device__ float4 g_boxes[BATCH * NANCH];                       // ~17.9 MB
__device__ float  g_probs[(size_t)BATCH * 20 * NANCH];          // ~89.4 MB
__device__ float  g_sc[BATCH * 20 * KTOP];                      // kept scores
__device__ float4 g_sb[BATCH * 20 * KTOP];                      // kept boxes

// ---------------- kernel 1: decode + softmax ---------------------------------
__global__ void prep_kernel(const float* __restrict__ loc,
                            const float* __restrict__ conf,
                            const float* __restrict__ dbox) {
    __shared__ float sc[128 * NCLS];
    int b   = blockIdx.y;
    int n0  = blockIdx.x * 128;
    int tid = threadIdx.x;              // 128 threads
    int nrows = NANCH - n0; if (nrows > 128) nrows = 128;

    const float* cp = conf + ((size_t)b * NANCH + n0) * NCLS;
    for (int i = tid; i < nrows * NCLS; i += 128) sc[i] = cp[i];
    __syncthreads();

    if (tid < nrows) {
        int n = n0 + tid;
        const float* x = &sc[tid * NCLS];
        float m = x[0];
#pragma unroll
        for (int c = 1; c < NCLS; c++) m = fmaxf(m, x[c]);
        float e[NCLS];
        float s = 0.f;
#pragma unroll
        for (int c = 0; c < NCLS; c++) { e[c] = expf(x[c] - m); s += e[c]; }

        // decode box
        float4 l = reinterpret_cast<const float4*>(loc)[(size_t)b * NANCH + n];
        float4 d = reinterpret_cast<const float4*>(dbox)[n];
        float cx = d.x + l.x * 0.1f * d.z;
        float cy = d.y + l.y * 0.1f * d.w;
        float w  = d.z * expf(l.z * 0.2f);
        float h  = d.w * expf(l.w * 0.2f);
        float x1 = cx - w * 0.5f;
        float y1 = cy - h * 0.5f;
        float x2 = x1 + w;
        float y2 = y1 + h;
        x1 = fminf(fmaxf(x1, 0.f), 1.f);
        y1 = fminf(fmaxf(y1, 0.f), 1.f);
        x2 = fminf(fmaxf(x2, 0.f), 1.f);
        y2 = fminf(fmaxf(y2, 0.f), 1.f);
        g_boxes[(size_t)b * NANCH + n] = make_float4(x1, y1, x2, y2);

        // class-major probs (skip background class 0); coalesced per-c row
#pragma unroll
        for (int c = 1; c < NCLS; c++)
            g_probs[((size_t)b * 20 + (c - 1)) * NANCH + n] = e[c] / s;
    }
}

// ---------------- shared helpers ---------------------------------------------
__device__ __forceinline__ unsigned warp_suffix_incl(unsigned x) {
    unsigned lane = threadIdx.x & 31;
#pragma unroll
    for (int d = 1; d < 32; d <<= 1) {
        unsigned t = __shfl_down_sync(0xffffffffu, x, d);
        if (lane + d < 32) x += t;
    }
    return x;   // sum of x over lanes [lane..31]
}

// exclusive suffix over 256 threads: sum of x over threads with tid' > tid
__device__ __forceinline__ unsigned block_excl_suffix_256(unsigned x, unsigned* s_warp) {
    int lane = threadIdx.x & 31, wid = threadIdx.x >> 5;
    unsigned inc = warp_suffix_incl(x);
    if (lane == 0) s_warp[wid] = inc;
    __syncthreads();
    unsigned above = 0;
#pragma unroll
    for (int w = 0; w < 8; w++) if (w > wid) above += s_warp[w];
    return (inc - x) + above;
}

// bitonic sort of 256 u64 keys, descending; one element per thread (blockDim=256).
// sub-warp stages use shfl; cross-warp stages use the provided 256-slot scratch.
__device__ __forceinline__ unsigned long long bitonic256_desc(
        unsigned long long v, unsigned long long* sh) {
    int tid = threadIdx.x;
#pragma unroll
    for (int kk = 2; kk <= 256; kk <<= 1) {
        for (int j = kk >> 1; j > 0; j >>= 1) {
            unsigned long long w;
            if (j >= 32) {
                __syncthreads();
                sh[tid] = v;
                __syncthreads();
                w = sh[tid ^ j];
            } else {
                w = __shfl_xor_sync(0xffffffffu, v, j);
            }
            bool keepMax = ((tid & j) == 0) == ((tid & kk) == 0);
            if (keepMax ? (w > v) : (w < v)) v = w;
        }
    }
    return v;
}

// ---------------- kernel 2: per-(batch,class) top-200 + greedy NMS -----------
// All valid scores s in (0.01, 1] => bits[31:26] constant (0x0F), so
// key16 = bits[25:10] is a complete order-preserving selection key, and a
// valid key16 is always > 0 (proof: key16==0 requires s < 0.0156 with top
// mantissa bits 0 => s == 2^-7 < 0.01, which fails the threshold).
__global__ __launch_bounds__(256) void nms_kernel() {
    __shared__ unsigned short keys16[NANCH];   // 17464 B smem key cache
    __shared__ unsigned hist[1024];
    __shared__ unsigned long long cand[256];
    __shared__ float4 sbox[KTOP];
    __shared__ float  sarea[KTOP];
    __shared__ unsigned char salive[KTOP];
    __shared__ unsigned s_warp[8];
    __shared__ int selBin, selKk;
    __shared__ unsigned selCnt, s_total, s_cnt;

    int c   = blockIdx.x;               // 0..19 -> class c+1
    int b   = blockIdx.y;
    int tid = threadIdx.x;              // 256 threads
    const float* __restrict__ row = g_probs + ((size_t)b * 20 + c) * NANCH;

    for (int i = tid; i < 1024; i += 256) hist[i] = 0;
    __syncthreads();

    // ---- pass A (the ONLY full global pass): key16 cache + 1024-bin hist ----
    for (int n = tid; n < NANCH; n += 256) {
        float s = row[n];
        unsigned k16 = 0u;
        if (s > CONF_T) {
            k16 = (__float_as_uint(s) >> 10) & 0xFFFFu;
            atomicAdd(&hist[k16 >> 6], 1u);          // bits[25:16]
        }
        keys16[n] = (unsigned short)k16;
    }
    __syncthreads();

    {   // parallel suffix selection over 1024 bins (4 bins/thread)
        unsigned h0 = hist[4*tid], h1 = hist[4*tid+1];
        unsigned h2 = hist[4*tid+2], h3 = hist[4*tid+3];
        unsigned s3 = h3, s2 = h2 + s3, s1 = h1 + s2, s0 = h0 + s1;
        unsigned E = block_excl_suffix_256(s0, s_warp);
        if (tid == 0) s_total = s0 + E;
        unsigned f0 = s0+E, f1 = s1+E, f2 = s2+E, f3 = s3+E, f4 = E;
        if (f0 >= KTOP && f1 < KTOP) { selBin = 4*tid+0; selKk = KTOP - (int)f1; }
        if (f1 >= KTOP && f2 < KTOP) { selBin = 4*tid+1; selKk = KTOP - (int)f2; }
        if (f2 >= KTOP && f3 < KTOP) { selBin = 4*tid+2; selKk = KTOP - (int)f3; }
        if (f3 >= KTOP && f4 < KTOP) { selBin = 4*tid+3; selKk = KTOP - (int)f4; }
    }
    __syncthreads();

    unsigned pivot16 = 1u;               // total<=200 -> take every valid key
    unsigned pivot32 = 0u;               // 0 => use the 16-bit smem path
    if (s_total > (unsigned)KTOP) {
        // ---- round 2 on the SMEM cache: low 6 bits within bin d0 ----
        int d0 = selBin, kk1 = selKk;
        if (tid < 64) hist[tid] = 0;
        __syncthreads();
        for (int n = tid; n < NANCH; n += 256) {
            unsigned k16 = keys16[n];
            if (k16 && (k16 >> 6) == (unsigned)d0)
                atomicAdd(&hist[k16 & 63u], 1u);
        }
        __syncthreads();
        {
            unsigned h = (tid < 64) ? hist[tid] : 0u;
            unsigned E = block_excl_suffix_256(h, s_warp);
            if (tid < 64 && h + E >= (unsigned)kk1 && E < (unsigned)kk1) {
                selBin = tid;
                selKk  = kk1 - (int)E;                   // rank within pivot bucket
                selCnt = (unsigned)(KTOP - kk1) + h + E; // total keys >= pivot16
            }
        }
        __syncthreads();
        pivot16 = ((unsigned)((unsigned)selBin) | ((unsigned)((KTOP - selCnt) & 0u))); // placeholder, fixed below
        pivot16 = (((unsigned)selKk, (unsigned)0u), 0u); // (dead) keep compiler honest
        pivot16 = (((unsigned)selBin) & 63u);
        pivot16 = 0u; // recompute cleanly:
        {
            int d1 = selBin;
            pivot16 = (((unsigned)d0) << 6) | (unsigned)d1;
        }

        if (selCnt > 256u) {
            // ---- rare path: too many 16-bit ties; exact 32-bit refine (R2) ----
            int kk1b = selKk;            // rank within the 16-bit pivot bucket
            // refine bits[9:2] (256 bins) among keys with key16 == pivot16
            hist[tid] = 0;
            __syncthreads();
            for (int n = tid; n < NANCH; n += 256) {
                unsigned k16 = keys16[n];
                if (k16 == pivot16) {
                    unsigned k = __float_as_uint(row[n]);
                    atomicAdd(&hist[(k >> 2) & 255u], 1u);
                }
            }
            __syncthreads();
            int d2; int kk2;
            {
                unsigned h = hist[tid];
                unsigned E = block_excl_suffix_256(h, s_warp);
                if (h + E >= (unsigned)kk1b && E < (unsigned)kk1b) { selBin = tid; selKk = kk1b - (int)E; }
            }
            __syncthreads();
            d2 = selBin; kk2 = selKk;
            // refine bits[1:0] (4 bins)
            if (tid < 4) hist[tid] = 0;
            __syncthreads();
            for (int n = tid; n < NANCH; n += 256) {
                unsigned k16 = keys16[n];
                if (k16 == pivot16) {
                    unsigned k = __float_as_uint(row[n]);
                    if (((k >> 2) & 255u) == (unsigned)d2)
                        atomicAdd(&hist[k & 3u], 1u);
                }
            }
            __syncthreads();
            {
                unsigned h = (tid < 4) ? hist[tid] : 0u;
                unsigned E = block_excl_suffix_256(h, s_warp);
                if (tid < 4 && h + E >= (unsigned)kk2 && E < (unsigned)kk2) { selBin = tid; }
            }
            __syncthreads();
            pivot32 = (0x0Fu << 26) | (pivot16 << 10) | ((unsigned)d2 << 2) | (unsigned)selBin;
        }
    }

    if (tid == 0) s_cnt = 0;
    __syncthreads();

    // ---- collect candidates from the SMEM cache ----
    // 64-bit key = (scorebits, ~index): stable descending == jax.lax.top_k.
    // Exact fp32 score fetched from global only for the <=256 candidates.
    if (pivot32 == 0u) {
        for (int n = tid; n < NANCH; n += 256) {
            unsigned k16 = keys16[n];
            if (k16 >= pivot16 && k16) {
                unsigned p = atomicAdd(&s_cnt, 1u);
                if (p < 256u) {
                    unsigned k = __float_as_uint(row[n]);
                    cand[p] = ((unsigned long long)k << 32) | (unsigned)(~n);
                }
            }
        }
    } else {
        for (int n = tid; n < NANCH; n += 256) {
            unsigned k16 = keys16[n];
            if (k16 > pivot16) {
                unsigned p = atomicAdd(&s_cnt, 1u);
                if (p < 256u) {
                    unsigned k = __float_as_uint(row[n]);
                    cand[p] = ((unsigned long long)k << 32) | (unsigned)(~n);
                }
            } else if (k16 == pivot16) {
                unsigned k = __float_as_uint(row[n]);
                if (k >= pivot32) {
                    unsigned p = atomicAdd(&s_cnt, 1u);
                    if (p < 256u)
                        cand[p] = ((unsigned long long)k << 32) | (unsigned)(~n);
                }
            }
        }
    }
    __syncthreads();
    unsigned mcnt = s_cnt < 256u ? s_cnt : 256u;
    unsigned long long v = (tid < (int)mcnt) ? cand[tid] : 0ull;
    v = bitonic256_desc(v, cand);
    __syncthreads();              // all scratch reads done before overwrite
    cand[tid] = v;
    __syncthreads();

    // ---- NMS state: own candidate in registers, broadcast state in shared ----
    bool   myAlive = false;
    float4 myBox   = make_float4(0.f, 0.f, 0.f, 0.f);
    float  myArea  = 0.f;
    if (tid < KTOP) {
        unsigned long long vv = cand[tid];
        if (vv) {
            unsigned n = ~(unsigned)(vv & 0xFFFFFFFFu);
            myBox  = g_boxes[(size_t)b * NANCH + n];
            myArea = (myBox.z - myBox.x) * (myBox.w - myBox.y);
            myAlive = true;
        }
        sbox[tid]   = myBox;
        sarea[tid]  = myArea;
        salive[tid] = myAlive ? 1 : 0;
    }
    __syncthreads();

    // greedy NMS: alive[i] is final by step i, so final alive == keep
    for (int i = 0; i < KTOP; i++) {
        if (salive[i]) {                          // uniform read
            if (tid > i && myAlive) {
                float4 bi = sbox[i];
                float xx1 = fmaxf(myBox.x, bi.x), yy1 = fmaxf(myBox.y, bi.y);
                float xx2 = fminf(myBox.z, bi.z), yy2 = fminf(myBox.w, bi.w);
                float inter = fmaxf(xx2 - xx1, 0.f) * fmaxf(yy2 - yy1, 0.f);
                float iou = inter / (myArea + sarea[i] - inter);
                if (!(iou <= NMS_T)) { myAlive = false; salive[tid] = 0; }  // NaN -> suppress
            }
        }
        __syncthreads();
    }

    if (tid < KTOP) {
        int o = (b * 20 + c) * KTOP + tid;
        g_sc[o] = myAlive ? __uint_as_float((unsigned)(cand[tid] >> 32)) : 0.f;
        g_sb[o] = myAlive ? myBox : make_float4(0.f, 0.f, 0.f, 0.f);
    }
}

// ---------------- kernel 3: global top-200 + per-class compaction ------------
__global__ __launch_bounds__(256) void final_kernel(float* __restrict__ out) {
    __shared__ unsigned hist[1024];
    __shared__ unsigned long long cand[256];
    __shared__ unsigned s_warp[8];
    __shared__ int selBin, selKk;
    __shared__ unsigned s_total, s_cnt;

    int b   = blockIdx.x;
    int tid = threadIdx.x;              // 256 threads
    const float* __restrict__ sc = g_sc + b * 4000;

    for (int i = tid; i < 1024; i += 256) hist[i] = 0;
    __syncthreads();
    for (int n = tid; n < 4000; n += 256) {
        float s = sc[n];                // kept scores are 0 or > 0.01
        if (s > 0.f) atomicAdd(&hist[(__float_as_uint(s) >> 16) & 1023u], 1u);
    }
    __syncthreads();
    {
        unsigned h0 = hist[4*tid], h1 = hist[4*tid+1], h2 = hist[4*tid+2], h3 = hist[4*tid+3];
        unsigned s3 = h3, s2 = h2 + s3, s1 = h1 + s2, s0 = h0 + s1;
        unsigned E = block_excl_suffix_256(s0, s_warp);
        if (tid == 0) s_total = s0 + E;
        unsigned f0 = s0+E, f1 = s1+E, f2 = s2+E, f3 = s3+E, f4 = E;
        if (f0 >= KTOP && f1 < KTOP) { selBin = 4*tid+0; selKk = KTOP - (int)f1; }
        if (f1 >= KTOP && f2 < KTOP) { selBin = 4*tid+1; selKk = KTOP - (int)f2; }
        if (f2 >= KTOP && f3 < KTOP) { selBin = 4*tid+2; selKk = KTOP - (int)f3; }
        if (f3 >= KTOP && f4 < KTOP) { selBin = 4*tid+3; selKk = KTOP - (int)f4; }
    }
    __syncthreads();

    unsigned pivot = 1u;
    if (s_total > KTOP) {
        int d0 = selBin, kk1 = selKk;
        hist[tid] = 0;
        __syncthreads();
        for (int n = tid; n < 4000; n += 256) {
            float s = sc[n];
            if (s > 0.f) {
                unsigned k = __float_as_uint(s);
                if (((k >> 16) & 1023u) == (unsigned)d0)
                    atomicAdd(&hist[(k >> 8) & 255u], 1u);
            }
        }
        __syncthreads();
        {
            unsigned h = hist[tid];
            unsigned E = block_excl_suffix_256(h, s_warp);
            if (h + E >= (unsigned)kk1 && E < (unsigned)kk1) { selBin = tid; selKk = kk1 - (int)E; }
        }
        __syncthreads();
        int d1 = selBin, kk2 = selKk;
        unsigned pref = ((unsigned)d0 << 8) | (unsigned)d1;
        hist[tid] = 0;
        __syncthreads();
        for (int n = tid; n < 4000; n += 256) {
            float s = sc[n];
            if (s > 0.f) {
                unsigned k = __float_as_uint(s);
                if (((k >> 8) & 0x3FFFFu) == pref)
                    atomicAdd(&hist[k & 255u], 1u);
            }
        }
        __syncthreads();
        {
            unsigned h = hist[tid];
            unsigned E = block_excl_suffix_256(h, s_warp);
            if (h + E >= (unsigned)kk2 && E < (unsigned)kk2) { selBin = tid; }
        }
        __syncthreads();
        pivot = (15u << 26) | ((unsigned)d0 << 16) | ((unsigned)d1 << 8) | (unsigned)selBin;
    }

    if (tid == 0) s_cnt = 0;
    __syncthreads();
    for (int n = tid; n < 4000; n += 256) {
        float s = sc[n];
        if (s > 0.f) {
            unsigned k = __float_as_uint(s);
            if (k >= pivot) {
                unsigned p = atomicAdd(&s_cnt, 1u);
                if (p < 256u) cand[p] = ((unsigned long long)k << 32) | (unsigned)(~n);
            }
        }
    }
    __syncthreads();
    unsigned mcnt = s_cnt < 256u ? s_cnt : 256u;
    unsigned long long v = (tid < (int)mcnt) ? cand[tid] : 0ull;
    v = bitonic256_desc(v, cand);
    __syncthreads();
    cand[tid] = v;
    __syncthreads();

    // zero the whole batch output (poisoned by harness), then compact
    float* o = out + (size_t)b * NCLS * KTOP * 5;
    for (int i = tid; i < NCLS * KTOP * 5; i += 256) o[i] = 0.f;
    __syncthreads();

    if (tid < 20) {
        int cnt = 0;
        for (int k = 0; k < KTOP; k++) {            // global top-200 only
            unsigned long long vv = cand[k];
            if (!vv) break;                          // zeros sort last
            unsigned idx = ~(unsigned)(vv & 0xFFFFFFFFu);
            if ((int)(idx / KTOP) == tid) {          // class tid+1
                float s = __uint_as_float((unsigned)(vv >> 32));
                float4 bx = g_sb[b * 4000 + idx];
                float* dst = o + ((size_t)(tid + 1) * KTOP + cnt) * 5;
                dst[0] = s;
                dst[1] = bx.x; dst[2] = bx.y; dst[3] = bx.z; dst[4] = bx.w;
                cnt++;
            }
        }
    }
}

// ---------------- launch ------------------------------------------------------
extern "C" void kernel_launch(void* const* d_in, const int* in_sizes, int n_in,
                              void* d_out, int out_size) {
    const float* loc  = (const float*)d_in[0];   // [128, 8732, 4]
    const float* conf = (const float*)d_in[1];   // [128, 8732, 21]
    const float* dbox = (const float*)d_in[2];   // [8732, 4]
    float* out = (float*)d_out;                  // [128, 21, 200, 5]

    dim3 g1((NANCH + 127) / 128, BATCH);
    prep_kernel<<<g1, 128>>>(loc, conf, dbox);

    dim3 g2(20, BATCH);
    nms_kernel<<<g2, 256>>>();

    final_kernel<<<BATCH, 256>>>(out);
}

// round 10
// speedup vs baseline: 1.5814x; 1.0695x over previous
#include <cuda_runtime.h>
#include <cuda_bf16.h>

#define BATCH 128
#define NANCH 8732
#define NCLS  21
#define KTOP  200
#define CONF_T 0.01f
#define NMS_T  0.45f

// ---------------- scratch (device globals; no allocations allowed) ----------
__device__ float4 g_boxes[BATCH * NANCH];                       // ~17.9 MB
__device__ float  g_probs[(size_t)BATCH * 20 * NANCH];          // ~89.4 MB
__device__ float  g_sc[BATCH * 20 * KTOP];                      // kept scores
__device__ float4 g_sb[BATCH * 20 * KTOP];                      // kept boxes

// ---------------- kernel 1: decode + softmax ---------------------------------
__global__ void prep_kernel(const float* __restrict__ loc,
                            const float* __restrict__ conf,
                            const float* __restrict__ dbox) {
    __shared__ float sc[128 * NCLS];
    int b   = blockIdx.y;
    int n0  = blockIdx.x * 128;
    int tid = threadIdx.x;              // 128 threads
    int nrows = NANCH - n0; if (nrows > 128) nrows = 128;

    const float* cp = conf + ((size_t)b * NANCH + n0) * NCLS;
    for (int i = tid; i < nrows * NCLS; i += 128) sc[i] = cp[i];
    __syncthreads();

    if (tid < nrows) {
        int n = n0 + tid;
        const float* x = &sc[tid * NCLS];
        float m = x[0];
#pragma unroll
        for (int c = 1; c < NCLS; c++) m = fmaxf(m, x[c]);
        float e[NCLS];
        float s = 0.f;
#pragma unroll
        for (int c = 0; c < NCLS; c++) { e[c] = expf(x[c] - m); s += e[c]; }

        // decode box
        float4 l = reinterpret_cast<const float4*>(loc)[(size_t)b * NANCH + n];
        float4 d = reinterpret_cast<const float4*>(dbox)[n];
        float cx = d.x + l.x * 0.1f * d.z;
        float cy = d.y + l.y * 0.1f * d.w;
        float w  = d.z * expf(l.z * 0.2f);
        float h  = d.w * expf(l.w * 0.2f);
        float x1 = cx - w * 0.5f;
        float y1 = cy - h * 0.5f;
        float x2 = x1 + w;
        float y2 = y1 + h;
        x1 = fminf(fmaxf(x1, 0.f), 1.f);
        y1 = fminf(fmaxf(y1, 0.f), 1.f);
        x2 = fminf(fmaxf(x2, 0.f), 1.f);
        y2 = fminf(fmaxf(y2, 0.f), 1.f);
        g_boxes[(size_t)b * NANCH + n] = make_float4(x1, y1, x2, y2);

        // class-major probs (skip background class 0); coalesced per-c row
#pragma unroll
        for (int c = 1; c < NCLS; c++)
            g_probs[((size_t)b * 20 + (c - 1)) * NANCH + n] = e[c] / s;
    }
}

// ---------------- shared helpers ---------------------------------------------
__device__ __forceinline__ unsigned warp_suffix_incl(unsigned x) {
    unsigned lane = threadIdx.x & 31;
#pragma unroll
    for (int d = 1; d < 32; d <<= 1) {
        unsigned t = __shfl_down_sync(0xffffffffu, x, d);
        if (lane + d < 32) x += t;
    }
    return x;   // sum of x over lanes [lane..31]
}

// exclusive suffix over 256 threads: sum of x over threads with tid' > tid
__device__ __forceinline__ unsigned block_excl_suffix_256(unsigned x, unsigned* s_warp) {
    int lane = threadIdx.x & 31, wid = threadIdx.x >> 5;
    unsigned inc = warp_suffix_incl(x);
    if (lane == 0) s_warp[wid] = inc;
    __syncthreads();
    unsigned above = 0;
#pragma unroll
    for (int w = 0; w < 8; w++) if (w > wid) above += s_warp[w];
    return (inc - x) + above;
}

// bitonic sort of 256 u64 keys, descending; one element per thread (blockDim=256).
// sub-warp stages use shfl; cross-warp stages use the provided 256-slot scratch.
__device__ __forceinline__ unsigned long long bitonic256_desc(
        unsigned long long v, unsigned long long* sh) {
    int tid = threadIdx.x;
#pragma unroll
    for (int kk = 2; kk <= 256; kk <<= 1) {
        for (int j = kk >> 1; j > 0; j >>= 1) {
            unsigned long long w;
            if (j >= 32) {
                __syncthreads();
                sh[tid] = v;
                __syncthreads();
                w = sh[tid ^ j];
            } else {
                w = __shfl_xor_sync(0xffffffffu, v, j);
            }
            bool keepMax = ((tid & j) == 0) == ((tid & kk) == 0);
            if (keepMax ? (w > v) : (w < v)) v = w;
        }
    }
    return v;
}

// ---------------- kernel 2: per-(batch,class) top-200 + greedy NMS -----------
// All valid scores s satisfy 0.01 < s <= 1  =>  float bits have bit31=0 and
// bits[30:26] = 01111. Only bits[25:0] vary. Histogram bits[25:16] (1024 bins).
// Common case: the count of keys at/above the selected bin's START (selCnt)
// is <= 256, so the loose bin-start pivot + full sort-256 yields the exact
// stable top-200 WITHOUT the two refine passes. Rare fallback: exact refine.
__global__ __launch_bounds__(256) void nms_kernel() {
    __shared__ unsigned hist[1024];
    __shared__ unsigned long long cand[256];
    __shared__ float4 sbox[KTOP];
    __shared__ float  sarea[KTOP];
    __shared__ unsigned char salive[KTOP];
    __shared__ unsigned s_warp[8];
    __shared__ int selBin, selKk;
    __shared__ unsigned selCnt, s_total, s_cnt;

    int c   = blockIdx.x;               // 0..19 -> class c+1
    int b   = blockIdx.y;
    int tid = threadIdx.x;              // 256 threads
    const float* __restrict__ row = g_probs + ((size_t)b * 20 + c) * NANCH;

    for (int i = tid; i < 1024; i += 256) hist[i] = 0;
    __syncthreads();

    // pass A: threshold + histogram bits[25:16] (row stays L2-resident)
    for (int n = tid; n < NANCH; n += 256) {
        float s = row[n];
        if (s > CONF_T) atomicAdd(&hist[(__float_as_uint(s) >> 16) & 1023u], 1u);
    }
    __syncthreads();

    {   // parallel suffix selection over 1024 bins (4 bins/thread)
        unsigned h0 = hist[4*tid], h1 = hist[4*tid+1];
        unsigned h2 = hist[4*tid+2], h3 = hist[4*tid+3];
        unsigned s3 = h3, s2 = h2 + s3, s1 = h1 + s2, s0 = h0 + s1;
        unsigned E = block_excl_suffix_256(s0, s_warp);
        if (tid == 0) s_total = s0 + E;
        unsigned f0 = s0+E, f1 = s1+E, f2 = s2+E, f3 = s3+E, f4 = E;
        if (f0 >= KTOP && f1 < KTOP) { selBin = 4*tid+0; selKk = KTOP-(int)f1; selCnt = f0; }
        if (f1 >= KTOP && f2 < KTOP) { selBin = 4*tid+1; selKk = KTOP-(int)f2; selCnt = f1; }
        if (f2 >= KTOP && f3 < KTOP) { selBin = 4*tid+2; selKk = KTOP-(int)f3; selCnt = f2; }
        if (f3 >= KTOP && f4 < KTOP) { selBin = 4*tid+3; selKk = KTOP-(int)f4; selCnt = f3; }
    }
    __syncthreads();

    unsigned pivot;
    if (s_total <= (unsigned)KTOP) {
        pivot = 1u;                      // take every thresholded key
    } else if (selCnt <= 256u) {
        // common path: collect ALL keys with top-10 bits >= selBin (selCnt of
        // them); the full sort extracts the exact stable top-200.
        pivot = (15u << 26) | ((unsigned)selBin << 16);
    } else {
        // rare path: exact refine, 8+8 bits (identical to the R2 baseline)
        int d0 = selBin, kk1 = selKk;
        hist[tid] = 0;
        __syncthreads();
        for (int n = tid; n < NANCH; n += 256) {
            float s = row[n];
            if (s > CONF_T) {
                unsigned k = __float_as_uint(s);
                if (((k >> 16) & 1023u) == (unsigned)d0)
                    atomicAdd(&hist[(k >> 8) & 255u], 1u);
            }
        }
        __syncthreads();
        {
            unsigned h = hist[tid];
            unsigned E = block_excl_suffix_256(h, s_warp);
            if (h + E >= (unsigned)kk1 && E < (unsigned)kk1) { selBin = tid; selKk = kk1-(int)E; }
        }
        __syncthreads();
        int d1 = selBin, kk2 = selKk;
        unsigned pref = ((unsigned)d0 << 8) | (unsigned)d1;   // bits[25:8]
        hist[tid] = 0;
        __syncthreads();
        for (int n = tid; n < NANCH; n += 256) {
            float s = row[n];
            if (s > CONF_T) {
                unsigned k = __float_as_uint(s);
                if (((k >> 8) & 0x3FFFFu) == pref)
                    atomicAdd(&hist[k & 255u], 1u);
            }
        }
        __syncthreads();
        {
            unsigned h = hist[tid];
            unsigned E = block_excl_suffix_256(h, s_warp);
            if (h + E >= (unsigned)kk2 && E < (unsigned)kk2) { selBin = tid; }
        }
        __syncthreads();
        pivot = (15u << 26) | ((unsigned)d0 << 16) | ((unsigned)d1 << 8) | (unsigned)selBin;
    }

    if (tid == 0) s_cnt = 0;
    __syncthreads();

    // collect candidates (>= pivot, > CONF_T); 64-bit key = (scorebits, ~index)
    // -> stable descending order identical to jax.lax.top_k
    for (int n = tid; n < NANCH; n += 256) {
        float s = row[n];
        if (s > CONF_T) {
            unsigned k = __float_as_uint(s);
            if (k >= pivot) {
                unsigned p = atomicAdd(&s_cnt, 1u);
                if (p < 256u) cand[p] = ((unsigned long long)k << 32) | (unsigned)(~n);
            }
        }
    }
    __syncthreads();
    unsigned mcnt = s_cnt < 256u ? s_cnt : 256u;
    unsigned long long v = (tid < (int)mcnt) ? cand[tid] : 0ull;
    v = bitonic256_desc(v, cand);
    __syncthreads();              // all scratch reads done before overwrite
    cand[tid] = v;
    __syncthreads();

    // ---- NMS state: own candidate in registers, broadcast state in shared ----
    bool   myAlive = false;
    float4 myBox   = make_float4(0.f, 0.f, 0.f, 0.f);
    float  myArea  = 0.f;
    if (tid < KTOP) {
        unsigned long long vv = cand[tid];
        if (vv) {
            unsigned n = ~(unsigned)(vv & 0xFFFFFFFFu);
            myBox  = g_boxes[(size_t)b * NANCH + n];
            myArea = (myBox.z - myBox.x) * (myBox.w - myBox.y);
            myAlive = true;
        }
        sbox[tid]   = myBox;
        sarea[tid]  = myArea;
        salive[tid] = myAlive ? 1 : 0;
    }
    __syncthreads();

    // greedy NMS: alive[i] is final by step i, so final alive == keep
    for (int i = 0; i < KTOP; i++) {
        if (salive[i]) {                          // uniform read
            if (tid > i && myAlive) {
                float4 bi = sbox[i];
                float xx1 = fmaxf(myBox.x, bi.x), yy1 = fmaxf(myBox.y, bi.y);
                float xx2 = fminf(myBox.z, bi.z), yy2 = fminf(myBox.w, bi.w);
                float inter = fmaxf(xx2 - xx1, 0.f) * fmaxf(yy2 - yy1, 0.f);
                float iou = inter / (myArea + sarea[i] - inter);
                if (!(iou <= NMS_T)) { myAlive = false; salive[tid] = 0; }  // NaN -> suppress
            }
        }
        __syncthreads();
    }

    if (tid < KTOP) {
        int o = (b * 20 + c) * KTOP + tid;
        g_sc[o] = myAlive ? __uint_as_float((unsigned)(cand[tid] >> 32)) : 0.f;
        g_sb[o] = myAlive ? myBox : make_float4(0.f, 0.f, 0.f, 0.f);
    }
}

// ---------------- kernel 3: global top-200 + per-class compaction ------------
__global__ __launch_bounds__(256) void final_kernel(float* __restrict__ out) {
    __shared__ unsigned hist[1024];
    __shared__ unsigned long long cand[256];
    __shared__ unsigned s_warp[8];
    __shared__ int selBin, selKk;
    __shared__ unsigned s_total, s_cnt;

    int b   = blockIdx.x;
    int tid = threadIdx.x;              // 256 threads
    const float* __restrict__ sc = g_sc + b * 4000;

    for (int i = tid; i < 1024; i += 256) hist[i] = 0;
    __syncthreads();
    for (int n = tid; n < 4000; n += 256) {
        float s = sc[n];                // kept scores are 0 or > 0.01
        if (s > 0.f) atomicAdd(&hist[(__float_as_uint(s) >> 16) & 1023u], 1u);
    }
    __syncthreads();
    {
        unsigned h0 = hist[4*tid], h1 = hist[4*tid+1], h2 = hist[4*tid+2], h3 = hist[4*tid+3];
        unsigned s3 = h3, s2 = h2 + s3, s1 = h1 + s2, s0 = h0 + s1;
        unsigned E = block_excl_suffix_256(s0, s_warp);
        if (tid == 0) s_total = s0 + E;
        unsigned f0 = s0+E, f1 = s1+E, f2 = s2+E, f3 = s3+E, f4 = E;
        if (f0 >= KTOP && f1 < KTOP) { selBin = 4*tid+0; selKk = KTOP - (int)f1; }
        if (f1 >= KTOP && f2 < KTOP) { selBin = 4*tid+1; selKk = KTOP - (int)f2; }
        if (f2 >= KTOP && f3 < KTOP) { selBin = 4*tid+2; selKk = KTOP - (int)f3; }
        if (f3 >= KTOP && f4 < KTOP) { selBin = 4*tid+3; selKk = KTOP - (int)f4; }
    }
    __syncthreads();

    unsigned pivot = 1u;
    if (s_total > KTOP) {
        int d0 = selBin, kk1 = selKk;
        hist[tid] = 0;
        __syncthreads();
        for (int n = tid; n < 4000; n += 256) {
            float s = sc[n];
            if (s > 0.f) {
                unsigned k = __float_as_uint(s);
                if (((k >> 16) & 1023u) == (unsigned)d0)
                    atomicAdd(&hist[(k >> 8) & 255u], 1u);
            }
        }
        __syncthreads();
        {
            unsigned h = hist[tid];
            unsigned E = block_excl_suffix_256(h, s_warp);
            if (h + E >= (unsigned)kk1 && E < (unsigned)kk1) { selBin = tid; selKk = kk1 - (int)E; }
        }
        __syncthreads();
        int d1 = selBin, kk2 = selKk;
        unsigned pref = ((unsigned)d0 << 8) | (unsigned)d1;
        hist[tid] = 0;
        __syncthreads();
        for (int n = tid; n < 4000; n += 256) {
            float s = sc[n];
            if (s > 0.f) {
                unsigned k = __float_as_uint(s);
                if (((k >> 8) & 0x3FFFFu) == pref)
                    atomicAdd(&hist[k & 255u], 1u);
            }
        }
        __syncthreads();
        {
            unsigned h = hist[tid];
            unsigned E = block_excl_suffix_256(h, s_warp);
            if (h + E >= (unsigned)kk2 && E < (unsigned)kk2) { selBin = tid; }
        }
        __syncthreads();
        pivot = (15u << 26) | ((unsigned)d0 << 16) | ((unsigned)d1 << 8) | (unsigned)selBin;
    }

    if (tid == 0) s_cnt = 0;
    __syncthreads();
    for (int n = tid; n < 4000; n += 256) {
        float s = sc[n];
        if (s > 0.f) {
            unsigned k = __float_as_uint(s);
            if (k >= pivot) {
                unsigned p = atomicAdd(&s_cnt, 1u);
                if (p < 256u) cand[p] = ((unsigned long long)k << 32) | (unsigned)(~n);
            }
        }
    }
    __syncthreads();
    unsigned mcnt = s_cnt < 256u ? s_cnt : 256u;
    unsigned long long v = (tid < (int)mcnt) ? cand[tid] : 0ull;
    v = bitonic256_desc(v, cand);
    __syncthreads();
    cand[tid] = v;
    __syncthreads();

    // zero the whole batch output (poisoned by harness), then compact
    float* o = out + (size_t)b * NCLS * KTOP * 5;
    for (int i = tid; i < NCLS * KTOP * 5; i += 256) o[i] = 0.f;
    __syncthreads();

    if (tid < 20) {
        int cnt = 0;
        for (int k = 0; k < KTOP; k++) {            // global top-200 only
            unsigned long long vv = cand[k];
            if (!vv) break;                          // zeros sort last
            unsigned idx = ~(unsigned)(vv & 0xFFFFFFFFu);
            if ((int)(idx / KTOP) == tid) {          // class tid+1
                float s = __uint_as_float((unsigned)(vv >> 32));
                float4 bx = g_sb[b * 4000 + idx];
                float* dst = o + ((size_t)(tid + 1) * KTOP + cnt) * 5;
                dst[0] = s;
                dst[1] = bx.x; dst[2] = bx.y; dst[3] = bx.z; dst[4] = bx.w;
                cnt++;
            }
        }
    }
}

// ---------------- launch ------------------------------------------------------
extern "C" void kernel_launch(void* const* d_in, const int* in_sizes, int n_in,
                              void* d_out, int out_size) {
    const float* loc  = (const float*)d_in[0];   // [128, 8732, 4]
    const float* conf = (const float*)d_in[1];   // [128, 8732, 21]
    const float* dbox = (const float*)d_in[2];   // [8732, 4]
    float* out = (float*)d_out;                  // [128, 21, 200, 5]

    dim3 g1((NANCH + 127) / 128, BATCH);
    prep_kernel<<<g1, 128>>>(loc, conf, dbox);

    dim3 g2(20, BATCH);
    nms_kernel<<<g2, 256>>>();

    final_kernel<<<BATCH, 256>>>(out);
}